// round 12
// baseline (speedup 1.0000x reference)
#include <cuda_runtime.h>
#include <cuda_fp16.h>
#include <cstddef>
#include <cstdint>

// Problem constants
constexpr int N_  = 25000;   // nodes
constexpr int E_  = 100000;  // edges
constexpr int H_  = 32;      // hidden
constexpr int NC_ = 8000;    // cliques
constexpr int A_  = 50000;   // node2clique assignments
constexpr int EC_ = 24000;   // clique edges
constexpr int L_  = 2;       // layers
constexpr int HH_ = 1024;    // H*H

// Scratch (device globals; no runtime allocation allowed)
__device__ __half g_Yh[(size_t)N_ * HH_];   // Y fp16 row-major: [n][k*32+o]
__device__ float g_z[N_ * H_];
__device__ float g_x[N_ * H_];
__device__ float g_x2[N_ * H_];
__device__ float g_c[NC_ * H_];
__device__ float g_c2[NC_ * H_];
__device__ float g_agg[N_ * H_];
__device__ float g_m[N_ * H_];
__device__ float g_cntE[N_];
__device__ float g_cntCE[NC_];
__device__ float g_cntAc[NC_];
__device__ float g_cntAn[N_];

static __device__ __forceinline__ uint32_t smemu32(const void* p) {
    return (uint32_t)__cvta_generic_to_shared(p);
}

// ---------------------------------------------------------------------------
__global__ void k_zero_all(float* __restrict__ cntE, float* __restrict__ cntCE,
                           float* __restrict__ cntAc, float* __restrict__ cntAn,
                           float* __restrict__ agg)
{
    int i = blockIdx.x * blockDim.x + threadIdx.x;
    int stride = gridDim.x * blockDim.x;
    for (int j = i; j < N_; j += stride) { cntE[j] = 0.f; cntAn[j] = 0.f; }
    for (int j = i; j < NC_; j += stride) { cntCE[j] = 0.f; cntAc[j] = 0.f; }
    for (int j = i; j < N_ * H_; j += stride) agg[j] = 0.f;
}

__global__ void k_count_all(const int* __restrict__ edst, const int* __restrict__ cedst,
                            const int* __restrict__ nid, const int* __restrict__ cid,
                            float* __restrict__ cntE, float* __restrict__ cntCE,
                            float* __restrict__ cntAc, float* __restrict__ cntAn)
{
    constexpr int T0 = E_, T1 = E_ + EC_, T2 = E_ + EC_ + A_, T3 = E_ + EC_ + A_ + A_;
    int i = blockIdx.x * blockDim.x + threadIdx.x;
    int stride = gridDim.x * blockDim.x;
    for (int j = i; j < T3; j += stride) {
        if (j < T0)      atomicAdd(&cntE[edst[j]], 1.f);
        else if (j < T1) atomicAdd(&cntCE[cedst[j - T0]], 1.f);
        else if (j < T2) atomicAdd(&cntAc[cid[j - T1]], 1.f);
        else             atomicAdd(&cntAn[nid[j - T2]], 1.f);
    }
}

// ---------------------------------------------------------------------------
// Tensor-core Y GEMM + folded z + OPTIONAL fused residual input.
// If base != nullptr: input row = base + agg/max(cnt,1); agg is cleared
// (consume-and-clear) and the computed input is also written to xout.
// Otherwise input row = xraw.
// W2 layout: W2[k*1024 + i*32 + o]; contraction index i (middle); staged
// permuted W2h[i][k*32+o]; b2 staged as cols [1024,1056).
constexpr int W2S = 1064;
constexpr int XS  = 40;
constexpr int SMEM_YTC = (32 * W2S + 64 * XS) * 2;

__global__ __launch_bounds__(256) void k_Y_tc(
    const float* __restrict__ xraw, const float* __restrict__ base,
    float* __restrict__ agg, const float* __restrict__ cnt,
    float* __restrict__ xout,
    const float* __restrict__ W2, const float* __restrict__ b2,
    __half* __restrict__ Yh, float* __restrict__ z, int rows)
{
    extern __shared__ __half smh[];
    __half* W2h = smh;             // [i=32][W2S]
    __half* xh  = smh + 32 * W2S;  // [64][XS]

    int tid = threadIdx.x, lane = tid & 31, w = tid >> 5;

    // Convert + PERMUTE W2 fp32 -> fp16 smem
    for (int idx = tid; idx < 8192; idx += 256) {
        float4 v = ((const float4*)W2)[idx];
        int g = idx * 4;
        int k = g >> 10, rem = g & 1023;
        int i = rem >> 5, o = rem & 31;
        __half2* dst = (__half2*)&W2h[i * W2S + k * 32 + o];
        dst[0] = __floats2half2_rn(v.x, v.y);
        dst[1] = __floats2half2_rn(v.z, v.w);
    }
    // b2 -> cols [1024,1056)
    {
        float4 vb = ((const float4*)b2)[tid];
        int g = tid * 4;
        int i = g >> 5, o = g & 31;
        __half2* dst = (__half2*)&W2h[i * W2S + 1024 + o];
        dst[0] = __floats2half2_rn(vb.x, vb.y);
        dst[1] = __floats2half2_rn(vb.z, vb.w);
    }
    // input tile -> fp16 smem (zero-padded); optional fused residual
    int n0 = blockIdx.x * 64;
    for (int i = tid; i < 64 * 32; i += 256) {
        int r = i >> 5, cc = i & 31;
        int gr = n0 + r;
        float v = 0.f;
        if (gr < rows) {
            size_t gi = (size_t)gr * 32 + cc;
            if (base) {
                float a = agg[gi];
                agg[gi] = 0.f;
                v = base[gi] + a / fmaxf(cnt[gr], 1.f);
                xout[gi] = v;
            } else {
                v = xraw[gi];
            }
        }
        xh[r * XS + cc] = __float2half_rn(v);
    }
    __syncthreads();

    // A fragments: 4 m-tiles x 2 k-steps
    uint32_t A[4][2][4];
    #pragma unroll
    for (int m = 0; m < 4; m++) {
        #pragma unroll
        for (int ks = 0; ks < 2; ks++) {
            uint32_t addr = smemu32(&xh[(m * 16 + (lane & 15)) * XS + ks * 16 + (lane >> 4) * 8]);
            asm volatile("ldmatrix.sync.aligned.m8n8.x4.shared.b16 {%0,%1,%2,%3}, [%4];"
                         : "=r"(A[m][ks][0]), "=r"(A[m][ks][1]),
                           "=r"(A[m][ks][2]), "=r"(A[m][ks][3])
                         : "r"(addr));
        }
    }

    int nb0 = w * 128;
    __half2* Y2 = (__half2*)Yh;
    #pragma unroll 4
    for (int n = 0; n < 16; n++) {
        int nb = nb0 + n * 8;
        uint32_t B[2][2];
        #pragma unroll
        for (int ks = 0; ks < 2; ks++) {
            uint32_t addr = smemu32(&W2h[(ks * 16 + (lane & 15)) * W2S + nb]);
            asm volatile("ldmatrix.sync.aligned.m8n8.x2.trans.shared.b16 {%0,%1}, [%2];"
                         : "=r"(B[ks][0]), "=r"(B[ks][1]) : "r"(addr));
        }
        #pragma unroll
        for (int m = 0; m < 4; m++) {
            float c0 = 0.f, c1 = 0.f, c2 = 0.f, c3 = 0.f;
            asm volatile(
                "mma.sync.aligned.m16n8k16.row.col.f32.f16.f16.f32 "
                "{%0,%1,%2,%3}, {%4,%5,%6,%7}, {%8,%9}, {%0,%1,%2,%3};"
                : "+f"(c0), "+f"(c1), "+f"(c2), "+f"(c3)
                : "r"(A[m][0][0]), "r"(A[m][0][1]), "r"(A[m][0][2]), "r"(A[m][0][3]),
                  "r"(B[0][0]), "r"(B[0][1]));
            asm volatile(
                "mma.sync.aligned.m16n8k16.row.col.f32.f16.f16.f32 "
                "{%0,%1,%2,%3}, {%4,%5,%6,%7}, {%8,%9}, {%0,%1,%2,%3};"
                : "+f"(c0), "+f"(c1), "+f"(c2), "+f"(c3)
                : "r"(A[m][1][0]), "r"(A[m][1][1]), "r"(A[m][1][2]), "r"(A[m][1][3]),
                  "r"(B[1][0]), "r"(B[1][1]));
            int r0 = n0 + m * 16 + (lane >> 2);
            int colh = (nb >> 1) + (lane & 3);
            if (r0 < rows)
                Y2[(size_t)r0 * 512 + colh] = __floats2half2_rn(c0, c1);
            if (r0 + 8 < rows)
                Y2[(size_t)(r0 + 8) * 512 + colh] = __floats2half2_rn(c2, c3);
        }
    }

    // z tile: warps 0..3, B cols [1024 + w*8, +8)
    if (w < 4) {
        int nb = 1024 + w * 8;
        uint32_t B[2][2];
        #pragma unroll
        for (int ks = 0; ks < 2; ks++) {
            uint32_t addr = smemu32(&W2h[(ks * 16 + (lane & 15)) * W2S + nb]);
            asm volatile("ldmatrix.sync.aligned.m8n8.x2.trans.shared.b16 {%0,%1}, [%2];"
                         : "=r"(B[ks][0]), "=r"(B[ks][1]) : "r"(addr));
        }
        #pragma unroll
        for (int m = 0; m < 4; m++) {
            float c0 = 0.f, c1 = 0.f, c2 = 0.f, c3 = 0.f;
            asm volatile(
                "mma.sync.aligned.m16n8k16.row.col.f32.f16.f16.f32 "
                "{%0,%1,%2,%3}, {%4,%5,%6,%7}, {%8,%9}, {%0,%1,%2,%3};"
                : "+f"(c0), "+f"(c1), "+f"(c2), "+f"(c3)
                : "r"(A[m][0][0]), "r"(A[m][0][1]), "r"(A[m][0][2]), "r"(A[m][0][3]),
                  "r"(B[0][0]), "r"(B[0][1]));
            asm volatile(
                "mma.sync.aligned.m16n8k16.row.col.f32.f16.f16.f32 "
                "{%0,%1,%2,%3}, {%4,%5,%6,%7}, {%8,%9}, {%0,%1,%2,%3};"
                : "+f"(c0), "+f"(c1), "+f"(c2), "+f"(c3)
                : "r"(A[m][1][0]), "r"(A[m][1][1]), "r"(A[m][1][2]), "r"(A[m][1][3]),
                  "r"(B[1][0]), "r"(B[1][1]));
            int r0 = n0 + m * 16 + (lane >> 2);
            int col = w * 8 + (lane & 3) * 2;
            if (r0 < rows)
                *(float2*)&z[(size_t)r0 * 32 + col] = make_float2(c0, c1);
            if (r0 + 8 < rows)
                *(float2*)&z[(size_t)(r0 + 8) * 32 + col] = make_float2(c2, c3);
        }
    }
}

// One warp per edge (R10-proven version). Yh plain row-major. lane = p*16+q
// handles o-pair (2q,2q+1) over k subset {p, p+2, ...}; shfl_xor(16)
// combines; per-lane scalar atomicAdd.
__global__ __launch_bounds__(256) void k_edge(
    const int* __restrict__ eidx, const float* __restrict__ ef,
    const float* __restrict__ w1, const float* __restrict__ b1,
    const __half* __restrict__ Yh, const float* __restrict__ z,
    float* __restrict__ agg, int ne)
{
    __shared__ float w1s[8 * 32];
    __shared__ float b1s[32];
    int tid = threadIdx.x;
    if (tid < 256) w1s[tid] = w1[tid];
    if (tid < 32)  b1s[tid] = b1[tid];
    __syncthreads();

    int lane = tid & 31;
    int e = blockIdx.x * 8 + (tid >> 5);
    if (e >= ne) return;

    int s = eidx[e];
    int d = eidx[ne + e];

    float h = b1s[lane];                    // h index = lane
    const float* efe = &ef[(size_t)e * 8];
    #pragma unroll
    for (int j = 0; j < 8; j++) h += efe[j] * w1s[j * 32 + lane];
    h = fmaxf(h, 0.f);

    int p = lane >> 4;                      // k parity
    float2 acc = make_float2(0.f, 0.f);
    const __half2* Yr2 = (const __half2*)&Yh[(size_t)s * 1024];
    #pragma unroll
    for (int it = 0; it < 16; it++) {
        int k = 2 * it + p;
        float hk = __shfl_sync(0xffffffffu, h, k);
        float2 v = __half22float2(Yr2[it * 32 + lane]);
        acc.x += hk * v.x;
        acc.y += hk * v.y;
    }
    acc.x += __shfl_xor_sync(0xffffffffu, acc.x, 16);
    acc.y += __shfl_xor_sync(0xffffffffu, acc.y, 16);

    int q = lane & 15;
    int o = 2 * q + p;
    float val = (p ? acc.y : acc.x) + z[(size_t)s * 32 + o];
    atomicAdd(&agg[(size_t)d * 32 + o], val);
}

// Fused: out = relu(agg/cnt + xin @ rw + rb) ; mout = out @ lw + lb
// Clears agg (consume-and-clear). One warp per row.
__global__ __launch_bounds__(256) void k_convlin(
    const float* __restrict__ xin, float* __restrict__ agg,
    const float* __restrict__ cnt,
    const float* __restrict__ rw, const float* __restrict__ rb,
    const float* __restrict__ lw, const float* __restrict__ lb,
    float* __restrict__ out, float* __restrict__ mout, int rows)
{
    __shared__ float rws[1024], lws[1024];
    __shared__ float rbs[32], lbs[32];
    int tid = threadIdx.x;
    for (int i = tid; i < 1024; i += 256) { rws[i] = rw[i]; lws[i] = lw[i]; }
    if (tid < 32) { rbs[tid] = rb[tid]; lbs[tid] = lb[tid]; }
    __syncthreads();

    int lane = tid & 31;
    int n = blockIdx.x * 8 + (tid >> 5);
    if (n >= rows) return;

    size_t base = (size_t)n * 32 + lane;
    float xr = xin[base];
    float acc = rbs[lane];
    #pragma unroll
    for (int i = 0; i < 32; i++)
        acc += __shfl_sync(0xffffffffu, xr, i) * rws[i * 32 + lane];
    float inv = 1.f / fmaxf(cnt[n], 1.f);
    acc += agg[base] * inv;
    agg[base] = 0.f;
    float o = fmaxf(acc, 0.f);
    out[base] = o;

    float macc = lbs[lane];
    #pragma unroll
    for (int i = 0; i < 32; i++)
        macc += __shfl_sync(0xffffffffu, o, i) * lws[i * 32 + lane];
    mout[base] = macc;
}

// One warp per assignment (R10-proven): agg[idx_out[a]] += m[idx_in[a]]
__global__ __launch_bounds__(256) void k_scatter(
    const int* __restrict__ idx_in, const int* __restrict__ idx_out,
    const float* __restrict__ m, float* __restrict__ agg, int n)
{
    int lane = threadIdx.x & 31;
    int a = blockIdx.x * 8 + (threadIdx.x >> 5);
    if (a >= n) return;
    atomicAdd(&agg[(size_t)idx_out[a] * 32 + lane],
              m[(size_t)idx_in[a] * 32 + lane]);
}

// out = base + agg/max(cnt,1); clears agg. (Final node output only.)
__global__ void k_resid(
    const float* __restrict__ base, float* __restrict__ agg,
    const float* __restrict__ cnt, float* __restrict__ out, int rows)
{
    int i = blockIdx.x * blockDim.x + threadIdx.x;
    if (i >= rows * 32) return;
    int n = i >> 5;
    out[i] = base[i] + agg[i] / fmaxf(cnt[n], 1.f);
    agg[i] = 0.f;
}

// ---------------------------------------------------------------------------
static inline int cdiv(int a, int b) { return (a + b - 1) / b; }

extern "C" void kernel_launch(void* const* d_in, const int* in_sizes, int n_in,
                              void* d_out, int out_size)
{
    const float* node_features   = (const float*)d_in[0];
    const int*   edge_index      = (const int*)d_in[1];
    const float* edge_features   = (const float*)d_in[2];
    const float* clique_features = (const float*)d_in[3];
    const int*   n2c_index       = (const int*)d_in[4];   // [2, A]: nid, cid
    const int*   cedge_index     = (const int*)d_in[5];
    const float* cedge_features  = (const float*)d_in[6];
    const float* nn1_w  = (const float*)d_in[7];
    const float* nn1_b  = (const float*)d_in[8];
    const float* nn2_w  = (const float*)d_in[9];
    const float* nn2_b  = (const float*)d_in[10];
    const float* root_w = (const float*)d_in[11];
    const float* root_b = (const float*)d_in[12];
    const float* n2c_w  = (const float*)d_in[13];
    const float* n2c_b  = (const float*)d_in[14];
    const float* cnn1_w = (const float*)d_in[15];
    const float* cnn1_b = (const float*)d_in[16];
    const float* cnn2_w = (const float*)d_in[17];
    const float* cnn2_b = (const float*)d_in[18];
    const float* croot_w = (const float*)d_in[19];
    const float* croot_b = (const float*)d_in[20];
    const float* c2n_w  = (const float*)d_in[21];
    const float* c2n_b  = (const float*)d_in[22];

    float *z, *x, *x2, *c, *c2, *agg, *m, *cntE, *cntCE, *cntAc, *cntAn;
    __half* Yh;
    cudaGetSymbolAddress((void**)&Yh, g_Yh);
    cudaGetSymbolAddress((void**)&z, g_z);
    cudaGetSymbolAddress((void**)&x, g_x);
    cudaGetSymbolAddress((void**)&x2, g_x2);
    cudaGetSymbolAddress((void**)&c, g_c);
    cudaGetSymbolAddress((void**)&c2, g_c2);
    cudaGetSymbolAddress((void**)&agg, g_agg);
    cudaGetSymbolAddress((void**)&m, g_m);
    cudaGetSymbolAddress((void**)&cntE, g_cntE);
    cudaGetSymbolAddress((void**)&cntCE, g_cntCE);
    cudaGetSymbolAddress((void**)&cntAc, g_cntAc);
    cudaGetSymbolAddress((void**)&cntAn, g_cntAn);

    float* out_x = (float*)d_out;                       // [N, H]
    float* out_c = (float*)d_out + (size_t)N_ * H_;     // [NC, H]

    cudaFuncSetAttribute(k_Y_tc, cudaFuncAttributeMaxDynamicSharedMemorySize, SMEM_YTC);

    k_zero_all<<<400, 256>>>(cntE, cntCE, cntAc, cntAn, agg);
    k_count_all<<<400, 256>>>(edge_index + E_, cedge_index + EC_,
                              n2c_index, n2c_index + A_,
                              cntE, cntCE, cntAc, cntAn);

    for (int l = 0; l < L_; l++) {
        const float* cin = (l == 0) ? clique_features : c;
        float* cout = (l == L_ - 1) ? out_c : c;

        // ---- node NNConv (layer>0: fused residual x = x2 + agg/cntAn) ----
        if (l == 0) {
            k_Y_tc<<<cdiv(N_, 64), 256, SMEM_YTC>>>(
                node_features, nullptr, nullptr, nullptr, nullptr,
                nn2_w + (size_t)l * 32768, nn2_b + (size_t)l * 1024, Yh, z, N_);
        } else {
            k_Y_tc<<<cdiv(N_, 64), 256, SMEM_YTC>>>(
                nullptr, x2, agg, cntAn, x,
                nn2_w + (size_t)l * 32768, nn2_b + (size_t)l * 1024, Yh, z, N_);
        }
        k_edge<<<cdiv(E_, 8), 256>>>(edge_index, edge_features,
                                     nn1_w + (size_t)l * 256, nn1_b + (size_t)l * 32,
                                     Yh, z, agg, E_);
        k_convlin<<<cdiv(N_, 8), 256>>>((l == 0) ? node_features : x, agg, cntE,
                                        root_w + (size_t)l * 1024, root_b + (size_t)l * 32,
                                        n2c_w + (size_t)l * 1024, n2c_b + (size_t)l * 32,
                                        x2, m, N_);
        k_scatter<<<cdiv(A_, 8), 256>>>(n2c_index, n2c_index + A_, m, agg, A_);

        // ---- clique NNConv (fused residual c2 = cin + agg/cntAc) ----
        k_Y_tc<<<cdiv(NC_, 64), 256, SMEM_YTC>>>(
            nullptr, cin, agg, cntAc, c2,
            cnn2_w + (size_t)l * 32768, cnn2_b + (size_t)l * 1024, Yh, z, NC_);
        k_edge<<<cdiv(EC_, 8), 256>>>(cedge_index, cedge_features,
                                      cnn1_w + (size_t)l * 256, cnn1_b + (size_t)l * 32,
                                      Yh, z, agg, EC_);
        k_convlin<<<cdiv(NC_, 8), 256>>>(c2, agg, cntCE,
                                         croot_w + (size_t)l * 1024, croot_b + (size_t)l * 32,
                                         c2n_w + (size_t)l * 1024, c2n_b + (size_t)l * 32,
                                         cout, m, NC_);
        k_scatter<<<cdiv(A_, 8), 256>>>(n2c_index + A_, n2c_index, m, agg, A_);

        // final layer: node residual straight to d_out
        if (l == L_ - 1)
            k_resid<<<cdiv(N_ * 32, 256), 256>>>(x2, agg, cntAn, out_x, N_);
    }
}

// round 13
// speedup vs baseline: 1.0940x; 1.0940x over previous
#include <cuda_runtime.h>
#include <cuda_fp16.h>
#include <cstddef>
#include <cstdint>

// Problem constants
constexpr int N_  = 25000;   // nodes
constexpr int E_  = 100000;  // edges
constexpr int H_  = 32;      // hidden
constexpr int NC_ = 8000;    // cliques
constexpr int A_  = 50000;   // node2clique assignments
constexpr int EC_ = 24000;   // clique edges
constexpr int L_  = 2;       // layers
constexpr int HH_ = 1024;    // H*H

// Scratch (device globals; no runtime allocation allowed)
__device__ __half g_Yh[(size_t)N_ * HH_];   // Y fp16 row-major: [n][k*32+o]
__device__ float g_z[N_ * H_];
__device__ float g_x[N_ * H_];
__device__ float g_x2[N_ * H_];
__device__ float g_c[NC_ * H_];
__device__ float g_c2[NC_ * H_];
__device__ float g_agg[N_ * H_];
__device__ float g_m[N_ * H_];
__device__ float g_cntE[N_];
__device__ float g_cntCE[NC_];
__device__ float g_cntAc[NC_];
__device__ float g_cntAn[N_];

static __device__ __forceinline__ uint32_t smemu32(const void* p) {
    return (uint32_t)__cvta_generic_to_shared(p);
}

// ---------------------------------------------------------------------------
__global__ void k_zero_all(float* __restrict__ cntE, float* __restrict__ cntCE,
                           float* __restrict__ cntAc, float* __restrict__ cntAn,
                           float* __restrict__ agg)
{
    int i = blockIdx.x * blockDim.x + threadIdx.x;
    int stride = gridDim.x * blockDim.x;
    for (int j = i; j < N_; j += stride) { cntE[j] = 0.f; cntAn[j] = 0.f; }
    for (int j = i; j < NC_; j += stride) { cntCE[j] = 0.f; cntAc[j] = 0.f; }
    for (int j = i; j < N_ * H_; j += stride) agg[j] = 0.f;
}

__global__ void k_count_all(const int* __restrict__ edst, const int* __restrict__ cedst,
                            const int* __restrict__ nid, const int* __restrict__ cid,
                            float* __restrict__ cntE, float* __restrict__ cntCE,
                            float* __restrict__ cntAc, float* __restrict__ cntAn)
{
    constexpr int T0 = E_, T1 = E_ + EC_, T2 = E_ + EC_ + A_, T3 = E_ + EC_ + A_ + A_;
    int i = blockIdx.x * blockDim.x + threadIdx.x;
    int stride = gridDim.x * blockDim.x;
    for (int j = i; j < T3; j += stride) {
        if (j < T0)      atomicAdd(&cntE[edst[j]], 1.f);
        else if (j < T1) atomicAdd(&cntCE[cedst[j - T0]], 1.f);
        else if (j < T2) atomicAdd(&cntAc[cid[j - T1]], 1.f);
        else             atomicAdd(&cntAn[nid[j - T2]], 1.f);
    }
}

// ---------------------------------------------------------------------------
// Tensor-core Y GEMM + folded z. (R10-proven version, no resid fusion.)
// W2 layout: W2[k*1024 + i*32 + o]; contraction index i (middle); staged
// permuted W2h[i][k*32+o]; b2 staged as cols [1024,1056).
constexpr int W2S = 1064;
constexpr int XS  = 40;
constexpr int SMEM_YTC = (32 * W2S + 64 * XS) * 2;

__global__ __launch_bounds__(256) void k_Y_tc(
    const float* __restrict__ x, const float* __restrict__ W2,
    const float* __restrict__ b2,
    __half* __restrict__ Yh, float* __restrict__ z, int rows)
{
    extern __shared__ __half smh[];
    __half* W2h = smh;             // [i=32][W2S]
    __half* xh  = smh + 32 * W2S;  // [64][XS]

    int tid = threadIdx.x, lane = tid & 31, w = tid >> 5;

    // Convert + PERMUTE W2 fp32 -> fp16 smem
    for (int idx = tid; idx < 8192; idx += 256) {
        float4 v = ((const float4*)W2)[idx];
        int g = idx * 4;
        int k = g >> 10, rem = g & 1023;
        int i = rem >> 5, o = rem & 31;
        __half2* dst = (__half2*)&W2h[i * W2S + k * 32 + o];
        dst[0] = __floats2half2_rn(v.x, v.y);
        dst[1] = __floats2half2_rn(v.z, v.w);
    }
    // b2 -> cols [1024,1056)
    {
        float4 vb = ((const float4*)b2)[tid];
        int g = tid * 4;
        int i = g >> 5, o = g & 31;
        __half2* dst = (__half2*)&W2h[i * W2S + 1024 + o];
        dst[0] = __floats2half2_rn(vb.x, vb.y);
        dst[1] = __floats2half2_rn(vb.z, vb.w);
    }
    // x tile -> fp16 smem (zero-padded)
    int n0 = blockIdx.x * 64;
    for (int i = tid; i < 64 * 32; i += 256) {
        int r = i >> 5, cc = i & 31;
        float v = (n0 + r < rows) ? x[(size_t)(n0 + r) * 32 + cc] : 0.f;
        xh[r * XS + cc] = __float2half_rn(v);
    }
    __syncthreads();

    // A fragments: 4 m-tiles x 2 k-steps
    uint32_t A[4][2][4];
    #pragma unroll
    for (int m = 0; m < 4; m++) {
        #pragma unroll
        for (int ks = 0; ks < 2; ks++) {
            uint32_t addr = smemu32(&xh[(m * 16 + (lane & 15)) * XS + ks * 16 + (lane >> 4) * 8]);
            asm volatile("ldmatrix.sync.aligned.m8n8.x4.shared.b16 {%0,%1,%2,%3}, [%4];"
                         : "=r"(A[m][ks][0]), "=r"(A[m][ks][1]),
                           "=r"(A[m][ks][2]), "=r"(A[m][ks][3])
                         : "r"(addr));
        }
    }

    int nb0 = w * 128;
    __half2* Y2 = (__half2*)Yh;
    #pragma unroll 4
    for (int n = 0; n < 16; n++) {
        int nb = nb0 + n * 8;
        uint32_t B[2][2];
        #pragma unroll
        for (int ks = 0; ks < 2; ks++) {
            uint32_t addr = smemu32(&W2h[(ks * 16 + (lane & 15)) * W2S + nb]);
            asm volatile("ldmatrix.sync.aligned.m8n8.x2.trans.shared.b16 {%0,%1}, [%2];"
                         : "=r"(B[ks][0]), "=r"(B[ks][1]) : "r"(addr));
        }
        #pragma unroll
        for (int m = 0; m < 4; m++) {
            float c0 = 0.f, c1 = 0.f, c2 = 0.f, c3 = 0.f;
            asm volatile(
                "mma.sync.aligned.m16n8k16.row.col.f32.f16.f16.f32 "
                "{%0,%1,%2,%3}, {%4,%5,%6,%7}, {%8,%9}, {%0,%1,%2,%3};"
                : "+f"(c0), "+f"(c1), "+f"(c2), "+f"(c3)
                : "r"(A[m][0][0]), "r"(A[m][0][1]), "r"(A[m][0][2]), "r"(A[m][0][3]),
                  "r"(B[0][0]), "r"(B[0][1]));
            asm volatile(
                "mma.sync.aligned.m16n8k16.row.col.f32.f16.f16.f32 "
                "{%0,%1,%2,%3}, {%4,%5,%6,%7}, {%8,%9}, {%0,%1,%2,%3};"
                : "+f"(c0), "+f"(c1), "+f"(c2), "+f"(c3)
                : "r"(A[m][1][0]), "r"(A[m][1][1]), "r"(A[m][1][2]), "r"(A[m][1][3]),
                  "r"(B[1][0]), "r"(B[1][1]));
            int r0 = n0 + m * 16 + (lane >> 2);
            int colh = (nb >> 1) + (lane & 3);
            if (r0 < rows)
                Y2[(size_t)r0 * 512 + colh] = __floats2half2_rn(c0, c1);
            if (r0 + 8 < rows)
                Y2[(size_t)(r0 + 8) * 512 + colh] = __floats2half2_rn(c2, c3);
        }
    }

    // z tile: warps 0..3, B cols [1024 + w*8, +8)
    if (w < 4) {
        int nb = 1024 + w * 8;
        uint32_t B[2][2];
        #pragma unroll
        for (int ks = 0; ks < 2; ks++) {
            uint32_t addr = smemu32(&W2h[(ks * 16 + (lane & 15)) * W2S + nb]);
            asm volatile("ldmatrix.sync.aligned.m8n8.x2.trans.shared.b16 {%0,%1}, [%2];"
                         : "=r"(B[ks][0]), "=r"(B[ks][1]) : "r"(addr));
        }
        #pragma unroll
        for (int m = 0; m < 4; m++) {
            float c0 = 0.f, c1 = 0.f, c2 = 0.f, c3 = 0.f;
            asm volatile(
                "mma.sync.aligned.m16n8k16.row.col.f32.f16.f16.f32 "
                "{%0,%1,%2,%3}, {%4,%5,%6,%7}, {%8,%9}, {%0,%1,%2,%3};"
                : "+f"(c0), "+f"(c1), "+f"(c2), "+f"(c3)
                : "r"(A[m][0][0]), "r"(A[m][0][1]), "r"(A[m][0][2]), "r"(A[m][0][3]),
                  "r"(B[0][0]), "r"(B[0][1]));
            asm volatile(
                "mma.sync.aligned.m16n8k16.row.col.f32.f16.f16.f32 "
                "{%0,%1,%2,%3}, {%4,%5,%6,%7}, {%8,%9}, {%0,%1,%2,%3};"
                : "+f"(c0), "+f"(c1), "+f"(c2), "+f"(c3)
                : "r"(A[m][1][0]), "r"(A[m][1][1]), "r"(A[m][1][2]), "r"(A[m][1][3]),
                  "r"(B[1][0]), "r"(B[1][1]));
            int r0 = n0 + m * 16 + (lane >> 2);
            int col = w * 8 + (lane & 3) * 2;
            if (r0 < rows)
                *(float2*)&z[(size_t)r0 * 32 + col] = make_float2(c0, c1);
            if (r0 + 8 < rows)
                *(float2*)&z[(size_t)(r0 + 8) * 32 + col] = make_float2(c2, c3);
        }
    }
}

// TWO edges per warp, loads interleaved for 2x memory-level parallelism.
// Per edge: lane = p*16+q handles o-pair (2q,2q+1) over k subset {p,p+2,...};
// shfl_xor(16) combines; per-lane scalar atomicAdd (R10-proven epilogue).
__global__ __launch_bounds__(256) void k_edge(
    const int* __restrict__ eidx, const float* __restrict__ ef,
    const float* __restrict__ w1, const float* __restrict__ b1,
    const __half* __restrict__ Yh, const float* __restrict__ z,
    float* __restrict__ agg, int ne)
{
    __shared__ float w1s[8 * 32];
    __shared__ float b1s[32];
    int tid = threadIdx.x;
    if (tid < 256) w1s[tid] = w1[tid];
    if (tid < 32)  b1s[tid] = b1[tid];
    __syncthreads();

    int lane = tid & 31;
    int e0 = (blockIdx.x * 8 + (tid >> 5)) * 2;
    if (e0 >= ne) return;
    int e1 = e0 + 1;
    bool has1 = (e1 < ne);

    int s0 = eidx[e0];
    int d0 = eidx[ne + e0];
    int s1 = has1 ? eidx[e1] : s0;
    int d1 = has1 ? eidx[ne + e1] : 0;

    // edge MLP for both edges
    float h0 = b1s[lane], h1 = b1s[lane];
    {
        const float* ef0 = &ef[(size_t)e0 * 8];
        const float* ef1 = &ef[(size_t)e1 * 8];
        #pragma unroll
        for (int j = 0; j < 8; j++) h0 += ef0[j] * w1s[j * 32 + lane];
        if (has1) {
            #pragma unroll
            for (int j = 0; j < 8; j++) h1 += ef1[j] * w1s[j * 32 + lane];
        }
    }
    h0 = fmaxf(h0, 0.f);
    h1 = fmaxf(h1, 0.f);

    int p = lane >> 4;                      // k parity
    float2 a0 = make_float2(0.f, 0.f);
    float2 a1 = make_float2(0.f, 0.f);
    const __half2* Yr0 = (const __half2*)&Yh[(size_t)s0 * 1024];
    const __half2* Yr1 = (const __half2*)&Yh[(size_t)s1 * 1024];
    #pragma unroll
    for (int it = 0; it < 16; it++) {
        int k = 2 * it + p;
        // interleaved loads: 2 independent 128B gathers in flight per step
        float2 v0 = __half22float2(Yr0[it * 32 + lane]);
        float2 v1 = __half22float2(Yr1[it * 32 + lane]);
        float hk0 = __shfl_sync(0xffffffffu, h0, k);
        float hk1 = __shfl_sync(0xffffffffu, h1, k);
        a0.x += hk0 * v0.x;  a0.y += hk0 * v0.y;
        a1.x += hk1 * v1.x;  a1.y += hk1 * v1.y;
    }
    a0.x += __shfl_xor_sync(0xffffffffu, a0.x, 16);
    a0.y += __shfl_xor_sync(0xffffffffu, a0.y, 16);
    a1.x += __shfl_xor_sync(0xffffffffu, a1.x, 16);
    a1.y += __shfl_xor_sync(0xffffffffu, a1.y, 16);

    int q = lane & 15;
    int o = 2 * q + p;
    float val0 = (p ? a0.y : a0.x) + z[(size_t)s0 * 32 + o];
    atomicAdd(&agg[(size_t)d0 * 32 + o], val0);
    if (has1) {
        float val1 = (p ? a1.y : a1.x) + z[(size_t)s1 * 32 + o];
        atomicAdd(&agg[(size_t)d1 * 32 + o], val1);
    }
}

// Fused: out = relu(agg/cnt + xin @ rw + rb) ; mout = out @ lw + lb
// Clears agg (consume-and-clear). One warp per row.
__global__ __launch_bounds__(256) void k_convlin(
    const float* __restrict__ xin, float* __restrict__ agg,
    const float* __restrict__ cnt,
    const float* __restrict__ rw, const float* __restrict__ rb,
    const float* __restrict__ lw, const float* __restrict__ lb,
    float* __restrict__ out, float* __restrict__ mout, int rows)
{
    __shared__ float rws[1024], lws[1024];
    __shared__ float rbs[32], lbs[32];
    int tid = threadIdx.x;
    for (int i = tid; i < 1024; i += 256) { rws[i] = rw[i]; lws[i] = lw[i]; }
    if (tid < 32) { rbs[tid] = rb[tid]; lbs[tid] = lb[tid]; }
    __syncthreads();

    int lane = tid & 31;
    int n = blockIdx.x * 8 + (tid >> 5);
    if (n >= rows) return;

    size_t base = (size_t)n * 32 + lane;
    float xr = xin[base];
    float acc = rbs[lane];
    #pragma unroll
    for (int i = 0; i < 32; i++)
        acc += __shfl_sync(0xffffffffu, xr, i) * rws[i * 32 + lane];
    float inv = 1.f / fmaxf(cnt[n], 1.f);
    acc += agg[base] * inv;
    agg[base] = 0.f;
    float o = fmaxf(acc, 0.f);
    out[base] = o;

    float macc = lbs[lane];
    #pragma unroll
    for (int i = 0; i < 32; i++)
        macc += __shfl_sync(0xffffffffu, o, i) * lws[i * 32 + lane];
    mout[base] = macc;
}

// One warp per assignment: agg[idx_out[a]] += m[idx_in[a]]
__global__ __launch_bounds__(256) void k_scatter(
    const int* __restrict__ idx_in, const int* __restrict__ idx_out,
    const float* __restrict__ m, float* __restrict__ agg, int n)
{
    int lane = threadIdx.x & 31;
    int a = blockIdx.x * 8 + (threadIdx.x >> 5);
    if (a >= n) return;
    atomicAdd(&agg[(size_t)idx_out[a] * 32 + lane],
              m[(size_t)idx_in[a] * 32 + lane]);
}

// out = base + agg/max(cnt,1); clears agg.
__global__ void k_resid(
    const float* __restrict__ base, float* __restrict__ agg,
    const float* __restrict__ cnt, float* __restrict__ out, int rows)
{
    int i = blockIdx.x * blockDim.x + threadIdx.x;
    if (i >= rows * 32) return;
    int n = i >> 5;
    out[i] = base[i] + agg[i] / fmaxf(cnt[n], 1.f);
    agg[i] = 0.f;
}

// ---------------------------------------------------------------------------
static inline int cdiv(int a, int b) { return (a + b - 1) / b; }

extern "C" void kernel_launch(void* const* d_in, const int* in_sizes, int n_in,
                              void* d_out, int out_size)
{
    const float* node_features   = (const float*)d_in[0];
    const int*   edge_index      = (const int*)d_in[1];
    const float* edge_features   = (const float*)d_in[2];
    const float* clique_features = (const float*)d_in[3];
    const int*   n2c_index       = (const int*)d_in[4];   // [2, A]: nid, cid
    const int*   cedge_index     = (const int*)d_in[5];
    const float* cedge_features  = (const float*)d_in[6];
    const float* nn1_w  = (const float*)d_in[7];
    const float* nn1_b  = (const float*)d_in[8];
    const float* nn2_w  = (const float*)d_in[9];
    const float* nn2_b  = (const float*)d_in[10];
    const float* root_w = (const float*)d_in[11];
    const float* root_b = (const float*)d_in[12];
    const float* n2c_w  = (const float*)d_in[13];
    const float* n2c_b  = (const float*)d_in[14];
    const float* cnn1_w = (const float*)d_in[15];
    const float* cnn1_b = (const float*)d_in[16];
    const float* cnn2_w = (const float*)d_in[17];
    const float* cnn2_b = (const float*)d_in[18];
    const float* croot_w = (const float*)d_in[19];
    const float* croot_b = (const float*)d_in[20];
    const float* c2n_w  = (const float*)d_in[21];
    const float* c2n_b  = (const float*)d_in[22];

    float *z, *x, *x2, *c, *c2, *agg, *m, *cntE, *cntCE, *cntAc, *cntAn;
    __half* Yh;
    cudaGetSymbolAddress((void**)&Yh, g_Yh);
    cudaGetSymbolAddress((void**)&z, g_z);
    cudaGetSymbolAddress((void**)&x, g_x);
    cudaGetSymbolAddress((void**)&x2, g_x2);
    cudaGetSymbolAddress((void**)&c, g_c);
    cudaGetSymbolAddress((void**)&c2, g_c2);
    cudaGetSymbolAddress((void**)&agg, g_agg);
    cudaGetSymbolAddress((void**)&m, g_m);
    cudaGetSymbolAddress((void**)&cntE, g_cntE);
    cudaGetSymbolAddress((void**)&cntCE, g_cntCE);
    cudaGetSymbolAddress((void**)&cntAc, g_cntAc);
    cudaGetSymbolAddress((void**)&cntAn, g_cntAn);

    float* out_x = (float*)d_out;                       // [N, H]
    float* out_c = (float*)d_out + (size_t)N_ * H_;     // [NC, H]

    cudaFuncSetAttribute(k_Y_tc, cudaFuncAttributeMaxDynamicSharedMemorySize, SMEM_YTC);

    k_zero_all<<<400, 256>>>(cntE, cntCE, cntAc, cntAn, agg);
    k_count_all<<<400, 256>>>(edge_index + E_, cedge_index + EC_,
                              n2c_index, n2c_index + A_,
                              cntE, cntCE, cntAc, cntAn);

    for (int l = 0; l < L_; l++) {
        const float* xin = (l == 0) ? node_features : x;
        const float* cin = (l == 0) ? clique_features : c;
        float* xout = (l == L_ - 1) ? out_x : x;
        float* cout = (l == L_ - 1) ? out_c : c;

        // ---- node NNConv + fused Node2Clique projection ----
        k_Y_tc<<<cdiv(N_, 64), 256, SMEM_YTC>>>(xin, nn2_w + (size_t)l * 32768,
                                                nn2_b + (size_t)l * 1024, Yh, z, N_);
        k_edge<<<cdiv(E_, 16), 256>>>(edge_index, edge_features,
                                      nn1_w + (size_t)l * 256, nn1_b + (size_t)l * 32,
                                      Yh, z, agg, E_);
        k_convlin<<<cdiv(N_, 8), 256>>>(xin, agg, cntE,
                                        root_w + (size_t)l * 1024, root_b + (size_t)l * 32,
                                        n2c_w + (size_t)l * 1024, n2c_b + (size_t)l * 32,
                                        x2, m, N_);
        k_scatter<<<cdiv(A_, 8), 256>>>(n2c_index, n2c_index + A_, m, agg, A_);
        k_resid<<<cdiv(NC_ * 32, 256), 256>>>(cin, agg, cntAc, c2, NC_);

        // ---- clique NNConv + fused Clique2Node projection ----
        k_Y_tc<<<cdiv(NC_, 64), 256, SMEM_YTC>>>(c2, cnn2_w + (size_t)l * 32768,
                                                 cnn2_b + (size_t)l * 1024, Yh, z, NC_);
        k_edge<<<cdiv(EC_, 16), 256>>>(cedge_index, cedge_features,
                                       cnn1_w + (size_t)l * 256, cnn1_b + (size_t)l * 32,
                                       Yh, z, agg, EC_);
        k_convlin<<<cdiv(NC_, 8), 256>>>(c2, agg, cntCE,
                                         croot_w + (size_t)l * 1024, croot_b + (size_t)l * 32,
                                         c2n_w + (size_t)l * 1024, c2n_b + (size_t)l * 32,
                                         cout, m, NC_);
        k_scatter<<<cdiv(A_, 8), 256>>>(n2c_index + A_, n2c_index, m, agg, A_);
        k_resid<<<cdiv(N_ * 32, 256), 256>>>(x2, agg, cntAn, xout, N_);
    }
}

// round 14
// speedup vs baseline: 1.2426x; 1.1359x over previous
#include <cuda_runtime.h>
#include <cuda_fp16.h>
#include <cstddef>
#include <cstdint>

// Problem constants
constexpr int N_  = 25000;   // nodes
constexpr int E_  = 100000;  // edges
constexpr int H_  = 32;      // hidden
constexpr int NC_ = 8000;    // cliques
constexpr int A_  = 50000;   // node2clique assignments
constexpr int EC_ = 24000;   // clique edges
constexpr int L_  = 2;       // layers
constexpr int HH_ = 1024;    // H*H

// Scratch (device globals; no runtime allocation allowed)
__device__ __half g_Yh[(size_t)N_ * HH_];   // Y fp16 row-major: [n][k*32+o]
__device__ float g_z[N_ * H_];
__device__ float g_x[N_ * H_];
__device__ float g_x2[N_ * H_];
__device__ float g_c[NC_ * H_];
__device__ float g_c2[NC_ * H_];
__device__ float g_agg[N_ * H_];
__device__ float g_m[N_ * H_];
__device__ float g_cntE[N_];
__device__ float g_cntCE[NC_];
__device__ float g_cntAc[NC_];
__device__ float g_cntAn[N_];

static __device__ __forceinline__ uint32_t smemu32(const void* p) {
    return (uint32_t)__cvta_generic_to_shared(p);
}

// ---------------------------------------------------------------------------
__global__ void k_zero_all(float* __restrict__ cntE, float* __restrict__ cntCE,
                           float* __restrict__ cntAc, float* __restrict__ cntAn,
                           float* __restrict__ agg)
{
    int i = blockIdx.x * blockDim.x + threadIdx.x;
    int stride = gridDim.x * blockDim.x;
    for (int j = i; j < N_; j += stride) { cntE[j] = 0.f; cntAn[j] = 0.f; }
    for (int j = i; j < NC_; j += stride) { cntCE[j] = 0.f; cntAc[j] = 0.f; }
    for (int j = i; j < N_ * H_; j += stride) agg[j] = 0.f;
}

__global__ void k_count_all(const int* __restrict__ edst, const int* __restrict__ cedst,
                            const int* __restrict__ nid, const int* __restrict__ cid,
                            float* __restrict__ cntE, float* __restrict__ cntCE,
                            float* __restrict__ cntAc, float* __restrict__ cntAn)
{
    constexpr int T0 = E_, T1 = E_ + EC_, T2 = E_ + EC_ + A_, T3 = E_ + EC_ + A_ + A_;
    int i = blockIdx.x * blockDim.x + threadIdx.x;
    int stride = gridDim.x * blockDim.x;
    for (int j = i; j < T3; j += stride) {
        if (j < T0)      atomicAdd(&cntE[edst[j]], 1.f);
        else if (j < T1) atomicAdd(&cntCE[cedst[j - T0]], 1.f);
        else if (j < T2) atomicAdd(&cntAc[cid[j - T1]], 1.f);
        else             atomicAdd(&cntAn[nid[j - T2]], 1.f);
    }
}

// ---------------------------------------------------------------------------
// Tensor-core Y GEMM + folded z. (R10-proven.)
// W2 layout: W2[k*1024 + i*32 + o]; contraction index i (middle); staged
// permuted W2h[i][k*32+o]; b2 staged as cols [1024,1056).
constexpr int W2S = 1064;
constexpr int XS  = 40;
constexpr int SMEM_YTC = (32 * W2S + 64 * XS) * 2;

__global__ __launch_bounds__(256) void k_Y_tc(
    const float* __restrict__ x, const float* __restrict__ W2,
    const float* __restrict__ b2,
    __half* __restrict__ Yh, float* __restrict__ z, int rows)
{
    extern __shared__ __half smh[];
    __half* W2h = smh;             // [i=32][W2S]
    __half* xh  = smh + 32 * W2S;  // [64][XS]

    int tid = threadIdx.x, lane = tid & 31, w = tid >> 5;

    // Convert + PERMUTE W2 fp32 -> fp16 smem
    for (int idx = tid; idx < 8192; idx += 256) {
        float4 v = ((const float4*)W2)[idx];
        int g = idx * 4;
        int k = g >> 10, rem = g & 1023;
        int i = rem >> 5, o = rem & 31;
        __half2* dst = (__half2*)&W2h[i * W2S + k * 32 + o];
        dst[0] = __floats2half2_rn(v.x, v.y);
        dst[1] = __floats2half2_rn(v.z, v.w);
    }
    // b2 -> cols [1024,1056)
    {
        float4 vb = ((const float4*)b2)[tid];
        int g = tid * 4;
        int i = g >> 5, o = g & 31;
        __half2* dst = (__half2*)&W2h[i * W2S + 1024 + o];
        dst[0] = __floats2half2_rn(vb.x, vb.y);
        dst[1] = __floats2half2_rn(vb.z, vb.w);
    }
    // x tile -> fp16 smem (zero-padded)
    int n0 = blockIdx.x * 64;
    for (int i = tid; i < 64 * 32; i += 256) {
        int r = i >> 5, cc = i & 31;
        float v = (n0 + r < rows) ? x[(size_t)(n0 + r) * 32 + cc] : 0.f;
        xh[r * XS + cc] = __float2half_rn(v);
    }
    __syncthreads();

    // A fragments: 4 m-tiles x 2 k-steps
    uint32_t A[4][2][4];
    #pragma unroll
    for (int m = 0; m < 4; m++) {
        #pragma unroll
        for (int ks = 0; ks < 2; ks++) {
            uint32_t addr = smemu32(&xh[(m * 16 + (lane & 15)) * XS + ks * 16 + (lane >> 4) * 8]);
            asm volatile("ldmatrix.sync.aligned.m8n8.x4.shared.b16 {%0,%1,%2,%3}, [%4];"
                         : "=r"(A[m][ks][0]), "=r"(A[m][ks][1]),
                           "=r"(A[m][ks][2]), "=r"(A[m][ks][3])
                         : "r"(addr));
        }
    }

    int nb0 = w * 128;
    __half2* Y2 = (__half2*)Yh;
    #pragma unroll 4
    for (int n = 0; n < 16; n++) {
        int nb = nb0 + n * 8;
        uint32_t B[2][2];
        #pragma unroll
        for (int ks = 0; ks < 2; ks++) {
            uint32_t addr = smemu32(&W2h[(ks * 16 + (lane & 15)) * W2S + nb]);
            asm volatile("ldmatrix.sync.aligned.m8n8.x2.trans.shared.b16 {%0,%1}, [%2];"
                         : "=r"(B[ks][0]), "=r"(B[ks][1]) : "r"(addr));
        }
        #pragma unroll
        for (int m = 0; m < 4; m++) {
            float c0 = 0.f, c1 = 0.f, c2 = 0.f, c3 = 0.f;
            asm volatile(
                "mma.sync.aligned.m16n8k16.row.col.f32.f16.f16.f32 "
                "{%0,%1,%2,%3}, {%4,%5,%6,%7}, {%8,%9}, {%0,%1,%2,%3};"
                : "+f"(c0), "+f"(c1), "+f"(c2), "+f"(c3)
                : "r"(A[m][0][0]), "r"(A[m][0][1]), "r"(A[m][0][2]), "r"(A[m][0][3]),
                  "r"(B[0][0]), "r"(B[0][1]));
            asm volatile(
                "mma.sync.aligned.m16n8k16.row.col.f32.f16.f16.f32 "
                "{%0,%1,%2,%3}, {%4,%5,%6,%7}, {%8,%9}, {%0,%1,%2,%3};"
                : "+f"(c0), "+f"(c1), "+f"(c2), "+f"(c3)
                : "r"(A[m][1][0]), "r"(A[m][1][1]), "r"(A[m][1][2]), "r"(A[m][1][3]),
                  "r"(B[1][0]), "r"(B[1][1]));
            int r0 = n0 + m * 16 + (lane >> 2);
            int colh = (nb >> 1) + (lane & 3);
            if (r0 < rows)
                Y2[(size_t)r0 * 512 + colh] = __floats2half2_rn(c0, c1);
            if (r0 + 8 < rows)
                Y2[(size_t)(r0 + 8) * 512 + colh] = __floats2half2_rn(c2, c3);
        }
    }

    // z tile: warps 0..3, B cols [1024 + w*8, +8)
    if (w < 4) {
        int nb = 1024 + w * 8;
        uint32_t B[2][2];
        #pragma unroll
        for (int ks = 0; ks < 2; ks++) {
            uint32_t addr = smemu32(&W2h[(ks * 16 + (lane & 15)) * W2S + nb]);
            asm volatile("ldmatrix.sync.aligned.m8n8.x2.trans.shared.b16 {%0,%1}, [%2];"
                         : "=r"(B[ks][0]), "=r"(B[ks][1]) : "r"(addr));
        }
        #pragma unroll
        for (int m = 0; m < 4; m++) {
            float c0 = 0.f, c1 = 0.f, c2 = 0.f, c3 = 0.f;
            asm volatile(
                "mma.sync.aligned.m16n8k16.row.col.f32.f16.f16.f32 "
                "{%0,%1,%2,%3}, {%4,%5,%6,%7}, {%8,%9}, {%0,%1,%2,%3};"
                : "+f"(c0), "+f"(c1), "+f"(c2), "+f"(c3)
                : "r"(A[m][0][0]), "r"(A[m][0][1]), "r"(A[m][0][2]), "r"(A[m][0][3]),
                  "r"(B[0][0]), "r"(B[0][1]));
            asm volatile(
                "mma.sync.aligned.m16n8k16.row.col.f32.f16.f16.f32 "
                "{%0,%1,%2,%3}, {%4,%5,%6,%7}, {%8,%9}, {%0,%1,%2,%3};"
                : "+f"(c0), "+f"(c1), "+f"(c2), "+f"(c3)
                : "r"(A[m][1][0]), "r"(A[m][1][1]), "r"(A[m][1][2]), "r"(A[m][1][3]),
                  "r"(B[1][0]), "r"(B[1][1]));
            int r0 = n0 + m * 16 + (lane >> 2);
            int col = w * 8 + (lane & 3) * 2;
            if (r0 < rows)
                *(float2*)&z[(size_t)r0 * 32 + col] = make_float2(c0, c1);
            if (r0 + 8 < rows)
                *(float2*)&z[(size_t)(r0 + 8) * 32 + col] = make_float2(c2, c3);
        }
    }
}

// TWO edges per warp (R13-proven). Per edge: lane = p*16+q handles o-pair
// (2q,2q+1) over k subset {p,p+2,...}; shfl_xor(16) combines; scalar atomics.
__global__ __launch_bounds__(256) void k_edge(
    const int* __restrict__ eidx, const float* __restrict__ ef,
    const float* __restrict__ w1, const float* __restrict__ b1,
    const __half* __restrict__ Yh, const float* __restrict__ z,
    float* __restrict__ agg, int ne)
{
    __shared__ float w1s[8 * 32];
    __shared__ float b1s[32];
    int tid = threadIdx.x;
    if (tid < 256) w1s[tid] = w1[tid];
    if (tid < 32)  b1s[tid] = b1[tid];
    __syncthreads();

    int lane = tid & 31;
    int e0 = (blockIdx.x * 8 + (tid >> 5)) * 2;
    if (e0 >= ne) return;
    int e1 = e0 + 1;
    bool has1 = (e1 < ne);

    int s0 = eidx[e0];
    int d0 = eidx[ne + e0];
    int s1 = has1 ? eidx[e1] : s0;
    int d1 = has1 ? eidx[ne + e1] : 0;

    float h0 = b1s[lane], h1 = b1s[lane];
    {
        const float* ef0 = &ef[(size_t)e0 * 8];
        const float* ef1 = &ef[(size_t)e1 * 8];
        #pragma unroll
        for (int j = 0; j < 8; j++) h0 += ef0[j] * w1s[j * 32 + lane];
        if (has1) {
            #pragma unroll
            for (int j = 0; j < 8; j++) h1 += ef1[j] * w1s[j * 32 + lane];
        }
    }
    h0 = fmaxf(h0, 0.f);
    h1 = fmaxf(h1, 0.f);

    int p = lane >> 4;
    float2 a0 = make_float2(0.f, 0.f);
    float2 a1 = make_float2(0.f, 0.f);
    const __half2* Yr0 = (const __half2*)&Yh[(size_t)s0 * 1024];
    const __half2* Yr1 = (const __half2*)&Yh[(size_t)s1 * 1024];
    #pragma unroll
    for (int it = 0; it < 16; it++) {
        int k = 2 * it + p;
        float2 v0 = __half22float2(Yr0[it * 32 + lane]);
        float2 v1 = __half22float2(Yr1[it * 32 + lane]);
        float hk0 = __shfl_sync(0xffffffffu, h0, k);
        float hk1 = __shfl_sync(0xffffffffu, h1, k);
        a0.x += hk0 * v0.x;  a0.y += hk0 * v0.y;
        a1.x += hk1 * v1.x;  a1.y += hk1 * v1.y;
    }
    a0.x += __shfl_xor_sync(0xffffffffu, a0.x, 16);
    a0.y += __shfl_xor_sync(0xffffffffu, a0.y, 16);
    a1.x += __shfl_xor_sync(0xffffffffu, a1.x, 16);
    a1.y += __shfl_xor_sync(0xffffffffu, a1.y, 16);

    int q = lane & 15;
    int o = 2 * q + p;
    float val0 = (p ? a0.y : a0.x) + z[(size_t)s0 * 32 + o];
    atomicAdd(&agg[(size_t)d0 * 32 + o], val0);
    if (has1) {
        float val1 = (p ? a1.y : a1.x) + z[(size_t)s1 * 32 + o];
        atomicAdd(&agg[(size_t)d1 * 32 + o], val1);
    }
}

// ---------------------------------------------------------------------------
// Tensor-core convlin: out = relu(xin@rw + rb + agg/cnt); mout = out@lw + lb.
// Clears agg. 128 threads, 64-row tile; warp w owns output cols [8w, 8w+8).
// Fragment layouts copied verbatim from validated k_Y_tc.
constexpr int CLS = 40;   // half stride (80B, 16B-aligned rows)

__global__ __launch_bounds__(128) void k_convlin_tc(
    const float* __restrict__ xin, float* __restrict__ agg,
    const float* __restrict__ cnt,
    const float* __restrict__ rw, const float* __restrict__ rb,
    const float* __restrict__ lw, const float* __restrict__ lb,
    float* __restrict__ out, float* __restrict__ mout, int rows)
{
    __shared__ __half Wr[32 * CLS], Wl[32 * CLS];
    __shared__ __half xh[64 * CLS], oh[64 * CLS];
    __shared__ float rbs[32], lbs[32];

    int tid = threadIdx.x, lane = tid & 31, w = tid >> 5;

    // stage rw, lw fp32 -> fp16 ([i=input][j=output], row-major, contraction=i)
    for (int t = tid; t < 256; t += 128) {
        int g = t * 4, i = g >> 5, j = g & 31;
        float4 v = ((const float4*)rw)[t];
        __half2* d = (__half2*)&Wr[i * CLS + j];
        d[0] = __floats2half2_rn(v.x, v.y);
        d[1] = __floats2half2_rn(v.z, v.w);
        float4 u = ((const float4*)lw)[t];
        __half2* d2 = (__half2*)&Wl[i * CLS + j];
        d2[0] = __floats2half2_rn(u.x, u.y);
        d2[1] = __floats2half2_rn(u.z, u.w);
    }
    if (tid < 32) { rbs[tid] = rb[tid]; lbs[tid] = lb[tid]; }

    int n0 = blockIdx.x * 64;
    for (int i = tid; i < 64 * 32; i += 128) {
        int r = i >> 5, cc = i & 31;
        float v = (n0 + r < rows) ? xin[(size_t)(n0 + r) * 32 + cc] : 0.f;
        xh[r * CLS + cc] = __float2half_rn(v);
    }
    __syncthreads();

    int nb = w * 8;
    int col = nb + (lane & 3) * 2;

    // ---- GEMM1: t = x @ rw ----
    {
        uint32_t A[4][2][4];
        #pragma unroll
        for (int m = 0; m < 4; m++) {
            #pragma unroll
            for (int ks = 0; ks < 2; ks++) {
                uint32_t addr = smemu32(&xh[(m * 16 + (lane & 15)) * CLS + ks * 16 + (lane >> 4) * 8]);
                asm volatile("ldmatrix.sync.aligned.m8n8.x4.shared.b16 {%0,%1,%2,%3}, [%4];"
                             : "=r"(A[m][ks][0]), "=r"(A[m][ks][1]),
                               "=r"(A[m][ks][2]), "=r"(A[m][ks][3])
                             : "r"(addr));
            }
        }
        uint32_t B[2][2];
        #pragma unroll
        for (int ks = 0; ks < 2; ks++) {
            uint32_t addr = smemu32(&Wr[(ks * 16 + (lane & 15)) * CLS + nb]);
            asm volatile("ldmatrix.sync.aligned.m8n8.x2.trans.shared.b16 {%0,%1}, [%2];"
                         : "=r"(B[ks][0]), "=r"(B[ks][1]) : "r"(addr));
        }
        #pragma unroll
        for (int m = 0; m < 4; m++) {
            float c0 = 0.f, c1 = 0.f, c2 = 0.f, c3 = 0.f;
            asm volatile(
                "mma.sync.aligned.m16n8k16.row.col.f32.f16.f16.f32 "
                "{%0,%1,%2,%3}, {%4,%5,%6,%7}, {%8,%9}, {%0,%1,%2,%3};"
                : "+f"(c0), "+f"(c1), "+f"(c2), "+f"(c3)
                : "r"(A[m][0][0]), "r"(A[m][0][1]), "r"(A[m][0][2]), "r"(A[m][0][3]),
                  "r"(B[0][0]), "r"(B[0][1]));
            asm volatile(
                "mma.sync.aligned.m16n8k16.row.col.f32.f16.f16.f32 "
                "{%0,%1,%2,%3}, {%4,%5,%6,%7}, {%8,%9}, {%0,%1,%2,%3};"
                : "+f"(c0), "+f"(c1), "+f"(c2), "+f"(c3)
                : "r"(A[m][1][0]), "r"(A[m][1][1]), "r"(A[m][1][2]), "r"(A[m][1][3]),
                  "r"(B[1][0]), "r"(B[1][1]));
            int rl = m * 16 + (lane >> 2);
            #pragma unroll
            for (int half = 0; half < 2; half++) {
                int lr = rl + half * 8;
                int gr = n0 + lr;
                float cv0 = half ? c2 : c0;
                float cv1 = half ? c3 : c1;
                float o0 = 0.f, o1 = 0.f;
                if (gr < rows) {
                    size_t gi = (size_t)gr * 32 + col;
                    float2 ag = *(float2*)&agg[gi];
                    float iv = 1.f / fmaxf(cnt[gr], 1.f);
                    o0 = fmaxf(cv0 + rbs[col] + ag.x * iv, 0.f);
                    o1 = fmaxf(cv1 + rbs[col + 1] + ag.y * iv, 0.f);
                    *(float2*)&out[gi] = make_float2(o0, o1);
                    *(float2*)&agg[gi] = make_float2(0.f, 0.f);   // consume-and-clear
                }
                *(__half2*)&oh[lr * CLS + col] = __floats2half2_rn(o0, o1);
            }
        }
    }
    __syncthreads();

    // ---- GEMM2: m = out @ lw + lb ----
    {
        uint32_t A[4][2][4];
        #pragma unroll
        for (int m = 0; m < 4; m++) {
            #pragma unroll
            for (int ks = 0; ks < 2; ks++) {
                uint32_t addr = smemu32(&oh[(m * 16 + (lane & 15)) * CLS + ks * 16 + (lane >> 4) * 8]);
                asm volatile("ldmatrix.sync.aligned.m8n8.x4.shared.b16 {%0,%1,%2,%3}, [%4];"
                             : "=r"(A[m][ks][0]), "=r"(A[m][ks][1]),
                               "=r"(A[m][ks][2]), "=r"(A[m][ks][3])
                             : "r"(addr));
            }
        }
        uint32_t B[2][2];
        #pragma unroll
        for (int ks = 0; ks < 2; ks++) {
            uint32_t addr = smemu32(&Wl[(ks * 16 + (lane & 15)) * CLS + nb]);
            asm volatile("ldmatrix.sync.aligned.m8n8.x2.trans.shared.b16 {%0,%1}, [%2];"
                         : "=r"(B[ks][0]), "=r"(B[ks][1]) : "r"(addr));
        }
        #pragma unroll
        for (int m = 0; m < 4; m++) {
            float c0 = 0.f, c1 = 0.f, c2 = 0.f, c3 = 0.f;
            asm volatile(
                "mma.sync.aligned.m16n8k16.row.col.f32.f16.f16.f32 "
                "{%0,%1,%2,%3}, {%4,%5,%6,%7}, {%8,%9}, {%0,%1,%2,%3};"
                : "+f"(c0), "+f"(c1), "+f"(c2), "+f"(c3)
                : "r"(A[m][0][0]), "r"(A[m][0][1]), "r"(A[m][0][2]), "r"(A[m][0][3]),
                  "r"(B[0][0]), "r"(B[0][1]));
            asm volatile(
                "mma.sync.aligned.m16n8k16.row.col.f32.f16.f16.f32 "
                "{%0,%1,%2,%3}, {%4,%5,%6,%7}, {%8,%9}, {%0,%1,%2,%3};"
                : "+f"(c0), "+f"(c1), "+f"(c2), "+f"(c3)
                : "r"(A[m][1][0]), "r"(A[m][1][1]), "r"(A[m][1][2]), "r"(A[m][1][3]),
                  "r"(B[1][0]), "r"(B[1][1]));
            int rl = m * 16 + (lane >> 2);
            #pragma unroll
            for (int half = 0; half < 2; half++) {
                int gr = n0 + rl + half * 8;
                if (gr < rows) {
                    float cv0 = (half ? c2 : c0) + lbs[col];
                    float cv1 = (half ? c3 : c1) + lbs[col + 1];
                    *(float2*)&mout[(size_t)gr * 32 + col] = make_float2(cv0, cv1);
                }
            }
        }
    }
}

// One warp per assignment: agg[idx_out[a]] += m[idx_in[a]]
__global__ __launch_bounds__(256) void k_scatter(
    const int* __restrict__ idx_in, const int* __restrict__ idx_out,
    const float* __restrict__ m, float* __restrict__ agg, int n)
{
    int lane = threadIdx.x & 31;
    int a = blockIdx.x * 8 + (threadIdx.x >> 5);
    if (a >= n) return;
    atomicAdd(&agg[(size_t)idx_out[a] * 32 + lane],
              m[(size_t)idx_in[a] * 32 + lane]);
}

// out = base + agg/max(cnt,1); clears agg.
__global__ void k_resid(
    const float* __restrict__ base, float* __restrict__ agg,
    const float* __restrict__ cnt, float* __restrict__ out, int rows)
{
    int i = blockIdx.x * blockDim.x + threadIdx.x;
    if (i >= rows * 32) return;
    int n = i >> 5;
    out[i] = base[i] + agg[i] / fmaxf(cnt[n], 1.f);
    agg[i] = 0.f;
}

// ---------------------------------------------------------------------------
static inline int cdiv(int a, int b) { return (a + b - 1) / b; }

extern "C" void kernel_launch(void* const* d_in, const int* in_sizes, int n_in,
                              void* d_out, int out_size)
{
    const float* node_features   = (const float*)d_in[0];
    const int*   edge_index      = (const int*)d_in[1];
    const float* edge_features   = (const float*)d_in[2];
    const float* clique_features = (const float*)d_in[3];
    const int*   n2c_index       = (const int*)d_in[4];   // [2, A]: nid, cid
    const int*   cedge_index     = (const int*)d_in[5];
    const float* cedge_features  = (const float*)d_in[6];
    const float* nn1_w  = (const float*)d_in[7];
    const float* nn1_b  = (const float*)d_in[8];
    const float* nn2_w  = (const float*)d_in[9];
    const float* nn2_b  = (const float*)d_in[10];
    const float* root_w = (const float*)d_in[11];
    const float* root_b = (const float*)d_in[12];
    const float* n2c_w  = (const float*)d_in[13];
    const float* n2c_b  = (const float*)d_in[14];
    const float* cnn1_w = (const float*)d_in[15];
    const float* cnn1_b = (const float*)d_in[16];
    const float* cnn2_w = (const float*)d_in[17];
    const float* cnn2_b = (const float*)d_in[18];
    const float* croot_w = (const float*)d_in[19];
    const float* croot_b = (const float*)d_in[20];
    const float* c2n_w  = (const float*)d_in[21];
    const float* c2n_b  = (const float*)d_in[22];

    float *z, *x, *x2, *c, *c2, *agg, *m, *cntE, *cntCE, *cntAc, *cntAn;
    __half* Yh;
    cudaGetSymbolAddress((void**)&Yh, g_Yh);
    cudaGetSymbolAddress((void**)&z, g_z);
    cudaGetSymbolAddress((void**)&x, g_x);
    cudaGetSymbolAddress((void**)&x2, g_x2);
    cudaGetSymbolAddress((void**)&c, g_c);
    cudaGetSymbolAddress((void**)&c2, g_c2);
    cudaGetSymbolAddress((void**)&agg, g_agg);
    cudaGetSymbolAddress((void**)&m, g_m);
    cudaGetSymbolAddress((void**)&cntE, g_cntE);
    cudaGetSymbolAddress((void**)&cntCE, g_cntCE);
    cudaGetSymbolAddress((void**)&cntAc, g_cntAc);
    cudaGetSymbolAddress((void**)&cntAn, g_cntAn);

    float* out_x = (float*)d_out;                       // [N, H]
    float* out_c = (float*)d_out + (size_t)N_ * H_;     // [NC, H]

    cudaFuncSetAttribute(k_Y_tc, cudaFuncAttributeMaxDynamicSharedMemorySize, SMEM_YTC);

    k_zero_all<<<400, 256>>>(cntE, cntCE, cntAc, cntAn, agg);
    k_count_all<<<400, 256>>>(edge_index + E_, cedge_index + EC_,
                              n2c_index, n2c_index + A_,
                              cntE, cntCE, cntAc, cntAn);

    for (int l = 0; l < L_; l++) {
        const float* xin = (l == 0) ? node_features : x;
        const float* cin = (l == 0) ? clique_features : c;
        float* xout = (l == L_ - 1) ? out_x : x;
        float* cout = (l == L_ - 1) ? out_c : c;

        // ---- node NNConv + fused Node2Clique projection ----
        k_Y_tc<<<cdiv(N_, 64), 256, SMEM_YTC>>>(xin, nn2_w + (size_t)l * 32768,
                                                nn2_b + (size_t)l * 1024, Yh, z, N_);
        k_edge<<<cdiv(E_, 16), 256>>>(edge_index, edge_features,
                                      nn1_w + (size_t)l * 256, nn1_b + (size_t)l * 32,
                                      Yh, z, agg, E_);
        k_convlin_tc<<<cdiv(N_, 64), 128>>>(xin, agg, cntE,
                                            root_w + (size_t)l * 1024, root_b + (size_t)l * 32,
                                            n2c_w + (size_t)l * 1024, n2c_b + (size_t)l * 32,
                                            x2, m, N_);
        k_scatter<<<cdiv(A_, 8), 256>>>(n2c_index, n2c_index + A_, m, agg, A_);
        k_resid<<<cdiv(NC_ * 32, 256), 256>>>(cin, agg, cntAc, c2, NC_);

        // ---- clique NNConv + fused Clique2Node projection ----
        k_Y_tc<<<cdiv(NC_, 64), 256, SMEM_YTC>>>(c2, cnn2_w + (size_t)l * 32768,
                                                 cnn2_b + (size_t)l * 1024, Yh, z, NC_);
        k_edge<<<cdiv(EC_, 16), 256>>>(cedge_index, cedge_features,
                                       cnn1_w + (size_t)l * 256, cnn1_b + (size_t)l * 32,
                                       Yh, z, agg, EC_);
        k_convlin_tc<<<cdiv(NC_, 64), 128>>>(c2, agg, cntCE,
                                             croot_w + (size_t)l * 1024, croot_b + (size_t)l * 32,
                                             c2n_w + (size_t)l * 1024, c2n_b + (size_t)l * 32,
                                             cout, m, NC_);
        k_scatter<<<cdiv(A_, 8), 256>>>(n2c_index + A_, n2c_index, m, agg, A_);
        k_resid<<<cdiv(N_ * 32, 256), 256>>>(x2, agg, cntAn, xout, N_);
    }
}